// round 3
// baseline (speedup 1.0000x reference)
#include <cuda_runtime.h>
#include <math.h>

// ---------------- problem constants ----------------
#define BB 8
#define TT 2048
#define CC 768
#define WDD 512
#define TDD 384
#define CDD 3072
#define HH1 384      // H1/2
#define HHS 1536     // CD/2
#define MTOT (BB*TT) // 16384

// ---------------- scratch (device globals; no runtime alloc) ----------------
__device__ float g_XLN [MTOT*CC];        // LN1(x)
__device__ float g_TMP [MTOT*CDD];       // pre-gate GEMM outputs (max width 3072)
__device__ float g_A   [MTOT*HHS];       // gated activations (max width 1536)
__device__ float g_H1  [MTOT*TDD];
__device__ float g_H2  [MTOT*TDD];
__device__ float g_MIX [BB*TDD*CC];
__device__ float g_X1  [MTOT*CC];
__device__ float g_XLN2[MTOT*CC];
__device__ float g_X2  [MTOT*CC];
__device__ float g_S1  [BB*HH1];
__device__ float g_S2  [BB*HH1];
__device__ float g_SS  [BB*HHS];

// ---------------- LayerNorm (one block per row, C=768) ----------------
__global__ __launch_bounds__(256) void ln_kernel(
    const float* __restrict__ X, const float* __restrict__ g,
    const float* __restrict__ b, float* __restrict__ Y)
{
    long row = blockIdx.x;
    const float* xr = X + row * CC;
    int t = threadIdx.x;
    float v0 = xr[t], v1 = xr[t + 256], v2 = xr[t + 512];
    float s  = v0 + v1 + v2;
    float s2 = v0*v0 + v1*v1 + v2*v2;
    __shared__ float sh[64];
    #pragma unroll
    for (int o = 16; o > 0; o >>= 1) {
        s  += __shfl_down_sync(0xffffffffu, s,  o);
        s2 += __shfl_down_sync(0xffffffffu, s2, o);
    }
    int w = t >> 5, l = t & 31;
    if (l == 0) { sh[w] = s; sh[w + 32] = s2; }
    __syncthreads();
    if (w == 0) {
        s  = (l < 8) ? sh[l]      : 0.f;
        s2 = (l < 8) ? sh[l + 32] : 0.f;
        #pragma unroll
        for (int o = 4; o > 0; o >>= 1) {
            s  += __shfl_down_sync(0xffffffffu, s,  o);
            s2 += __shfl_down_sync(0xffffffffu, s2, o);
        }
        if (l == 0) { sh[0] = s; sh[1] = s2; }
    }
    __syncthreads();
    float mu  = sh[0] * (1.0f / CC);
    float var = sh[1] * (1.0f / CC) - mu * mu;
    float inv = rsqrtf(var + 1e-6f);
    float* yr = Y + row * CC;
    yr[t]       = (v0 - mu) * inv * g[t]       + b[t];
    yr[t + 256] = (v1 - mu) * inv * g[t + 256] + b[t + 256];
    yr[t + 512] = (v2 - mu) * inv * g[t + 512] + b[t + 512];
}

// ---------------- style vector: S[b,n] = w_row[b] @ sW + sb ----------------
__global__ __launch_bounds__(128) void style_kernel(
    const float* __restrict__ w, int wOff,
    const float* __restrict__ sW, const float* __restrict__ sb,
    float* __restrict__ S, int N)
{
    int b = blockIdx.y;
    int n = blockIdx.x * 128 + threadIdx.x;
    const float* wr = w + (long)b * 2 * WDD + wOff;
    __shared__ float ws[WDD];
    for (int i = threadIdx.x; i < WDD; i += 128) ws[i] = wr[i];
    __syncthreads();
    float acc = sb[n];
    #pragma unroll 4
    for (int k = 0; k < WDD; k++) acc = fmaf(ws[k], sW[(long)k * N + n], acc);
    S[(long)b * N + n] = acc;
}

// ---------------- gate: A = h_a * sigmoid(h_g) [* S(b)] ----------------
__global__ __launch_bounds__(256) void gate_kernel(
    const float* __restrict__ H, const float* __restrict__ S,
    float* __restrict__ A, int Hh)
{
    long idx = (long)blockIdx.x * 256 + threadIdx.x;
    long row = idx / Hh;
    int  j   = (int)(idx - row * Hh);
    const float* hr = H + row * (2L * Hh);
    float av = hr[j];
    float gv = hr[j + Hh];
    float r  = av * (1.0f / (1.0f + expf(-gv)));
    if (S) r *= S[(row / TT) * (long)Hh + j];
    A[idx] = r;
}

// ---------------- tiled SGEMM 128x128x16, 256 thr, 8x8 micro-tile ----------------
// EPI: 0=bias(opt), 1=gelu(exact), 2=bias(opt)+residual
template<int EPI, bool TRANSA>
__global__ __launch_bounds__(256) void gemm_kernel(
    const float* __restrict__ A, long sA, int lda,
    const float* __restrict__ Bm, long sB, int ldb,
    float* __restrict__ Cm, long sC, int ldc,
    const float* __restrict__ bias,
    const float* __restrict__ Res, long sRes,
    int K)
{
    const int bz = blockIdx.z;
    A  += (long)bz * sA;
    Bm += (long)bz * sB;
    Cm += (long)bz * sC;
    if (EPI == 2) Res += (long)bz * sRes;

    const int bm = blockIdx.y * 128;
    const int bn = blockIdx.x * 128;
    const int tid = threadIdx.x;
    const int tx = tid & 15, ty = tid >> 4;

    __shared__ float As[16][128];
    __shared__ float Bs[16][128];

    float acc[8][8];
    #pragma unroll
    for (int i = 0; i < 8; i++)
        #pragma unroll
        for (int j = 0; j < 8; j++) acc[i][j] = 0.f;

    for (int k0 = 0; k0 < K; k0 += 16) {
        if (!TRANSA) {
            #pragma unroll
            for (int i = 0; i < 2; i++) {
                int t = tid + i * 256;          // 0..511
                int row = t >> 2;               // 0..127
                int kc  = (t & 3) * 4;          // 0,4,8,12
                float4 v = *(const float4*)&A[(long)(bm + row) * lda + k0 + kc];
                As[kc + 0][row] = v.x; As[kc + 1][row] = v.y;
                As[kc + 2][row] = v.z; As[kc + 3][row] = v.w;
            }
        } else {
            #pragma unroll
            for (int i = 0; i < 2; i++) {
                int t = tid + i * 256;
                int kr = t >> 5;                // 0..15
                int mc = (t & 31) * 4;          // 0..124
                *(float4*)&As[kr][mc] =
                    *(const float4*)&A[(long)(k0 + kr) * lda + bm + mc];
            }
        }
        #pragma unroll
        for (int i = 0; i < 2; i++) {
            int t = tid + i * 256;
            int kr = t >> 5;
            int nc = (t & 31) * 4;
            *(float4*)&Bs[kr][nc] =
                *(const float4*)&Bm[(long)(k0 + kr) * ldb + bn + nc];
        }
        __syncthreads();

        #pragma unroll
        for (int kk = 0; kk < 16; kk++) {
            float a[8], b[8];
            *(float4*)&a[0] = *(float4*)&As[kk][ty * 8];
            *(float4*)&a[4] = *(float4*)&As[kk][ty * 8 + 4];
            *(float4*)&b[0] = *(float4*)&Bs[kk][tx * 8];
            *(float4*)&b[4] = *(float4*)&Bs[kk][tx * 8 + 4];
            #pragma unroll
            for (int i = 0; i < 8; i++)
                #pragma unroll
                for (int j = 0; j < 8; j++)
                    acc[i][j] = fmaf(a[i], b[j], acc[i][j]);
        }
        __syncthreads();
    }

    #pragma unroll
    for (int i = 0; i < 8; i++) {
        long row = bm + ty * 8 + i;
        #pragma unroll
        for (int j = 0; j < 8; j += 4) {
            int col = bn + tx * 8 + j;
            float4 v = make_float4(acc[i][j], acc[i][j+1], acc[i][j+2], acc[i][j+3]);
            if (EPI != 1 && bias) {
                v.x += bias[col];   v.y += bias[col+1];
                v.z += bias[col+2]; v.w += bias[col+3];
            }
            if (EPI == 1) {
                v.x = 0.5f * v.x * (1.f + erff(v.x * 0.70710678118f));
                v.y = 0.5f * v.y * (1.f + erff(v.y * 0.70710678118f));
                v.z = 0.5f * v.z * (1.f + erff(v.z * 0.70710678118f));
                v.w = 0.5f * v.w * (1.f + erff(v.w * 0.70710678118f));
            }
            if (EPI == 2) {
                float4 r = *(const float4*)&Res[row * ldc + col];
                v.x += r.x; v.y += r.y; v.z += r.z; v.w += r.w;
            }
            *(float4*)&Cm[row * (long)ldc + col] = v;
        }
    }
}

// ---------------- host orchestration ----------------
extern "C" void kernel_launch(void* const* d_in, const int* in_sizes, int n_in,
                              void* d_out, int out_size)
{
    const float* x     = (const float*)d_in[0];
    const float* w     = (const float*)d_in[1];
    const float* ln1_g = (const float*)d_in[2];
    const float* ln1_b = (const float*)d_in[3];
    const float* ln2_g = (const float*)d_in[4];
    const float* ln2_b = (const float*)d_in[5];
    const float* g1_W  = (const float*)d_in[6];
    const float* g1_b  = (const float*)d_in[7];
    const float* s1_W  = (const float*)d_in[8];
    const float* s1_b  = (const float*)d_in[9];
    const float* m1_W  = (const float*)d_in[10];
    const float* m1_b  = (const float*)d_in[11];
    const float* g2_W  = (const float*)d_in[12];
    const float* g2_b  = (const float*)d_in[13];
    const float* s2_W  = (const float*)d_in[14];
    const float* s2_b  = (const float*)d_in[15];
    const float* m2_W  = (const float*)d_in[16];
    const float* m2_b  = (const float*)d_in[17];
    const float* gs_W  = (const float*)d_in[18];
    const float* gs_b  = (const float*)d_in[19];
    const float* ss_W  = (const float*)d_in[20];
    const float* ss_b  = (const float*)d_in[21];
    const float* ms_W  = (const float*)d_in[22];
    const float* ms_b  = (const float*)d_in[23];
    const float* r1_W  = (const float*)d_in[24];
    const float* r1_b  = (const float*)d_in[25];
    const float* r2_W  = (const float*)d_in[26];
    const float* r2_b  = (const float*)d_in[27];
    float* out = (float*)d_out;

    float *XLN, *TMP, *Ab, *H1, *H2, *MIX, *X1, *XLN2, *X2, *S1, *S2, *SS;
    cudaGetSymbolAddress((void**)&XLN,  g_XLN);
    cudaGetSymbolAddress((void**)&TMP,  g_TMP);
    cudaGetSymbolAddress((void**)&Ab,   g_A);
    cudaGetSymbolAddress((void**)&H1,   g_H1);
    cudaGetSymbolAddress((void**)&H2,   g_H2);
    cudaGetSymbolAddress((void**)&MIX,  g_MIX);
    cudaGetSymbolAddress((void**)&X1,   g_X1);
    cudaGetSymbolAddress((void**)&XLN2, g_XLN2);
    cudaGetSymbolAddress((void**)&X2,   g_X2);
    cudaGetSymbolAddress((void**)&S1,   g_S1);
    cudaGetSymbolAddress((void**)&S2,   g_S2);
    cudaGetSymbolAddress((void**)&SS,   g_SS);

    // 1. LN1
    ln_kernel<<<MTOT, 256>>>(x, ln1_g, ln1_b, XLN);

    // 2. style vectors (w0 for s1/s2, w1 for ss)
    style_kernel<<<dim3(HH1/128, BB), 128>>>(w, 0,   s1_W, s1_b, S1, HH1);
    style_kernel<<<dim3(HH1/128, BB), 128>>>(w, 0,   s2_W, s2_b, S2, HH1);
    style_kernel<<<dim3(HHS/128, BB), 128>>>(w, WDD, ss_W, ss_b, SS, HHS);

    // 3-5. GLU #1: h = XLN@g1_W+g1_b ; gate*S1 ; H1 = A@m1_W+m1_b
    gemm_kernel<0,false><<<dim3(CC/128, MTOT/128, 1), 256>>>(
        XLN, 0, CC, g1_W, 0, CC, TMP, 0, CC, g1_b, nullptr, 0, CC);
    gate_kernel<<<(long)MTOT*HH1/256, 256>>>(TMP, S1, Ab, HH1);
    gemm_kernel<0,false><<<dim3(TDD/128, MTOT/128, 1), 256>>>(
        Ab, 0, HH1, m1_W, 0, TDD, H1, 0, TDD, m1_b, nullptr, 0, TDD);

    // 6. GLU #2 -> H2
    gemm_kernel<0,false><<<dim3(CC/128, MTOT/128, 1), 256>>>(
        XLN, 0, CC, g2_W, 0, CC, TMP, 0, CC, g2_b, nullptr, 0, CC);
    gate_kernel<<<(long)MTOT*HH1/256, 256>>>(TMP, S2, Ab, HH1);
    gemm_kernel<0,false><<<dim3(TDD/128, MTOT/128, 1), 256>>>(
        Ab, 0, HH1, m2_W, 0, TDD, H2, 0, TDD, m2_b, nullptr, 0, TDD);

    // 7. mix[b] = gelu(h1[b]^T @ XLN[b])   (transA, batched, K=T)
    gemm_kernel<1,true><<<dim3(CC/128, TDD/128, BB), 256>>>(
        H1, (long)TT*TDD, TDD, XLN, (long)TT*CC, CC,
        MIX, (long)TDD*CC, CC, nullptr, nullptr, 0, TT);

    // 8. X1 = XLN + h2[b] @ mix[b]   (batched, K=TD)
    gemm_kernel<2,false><<<dim3(CC/128, TT/128, BB), 256>>>(
        H2, (long)TT*TDD, TDD, MIX, (long)TDD*CC, CC,
        X1, (long)TT*CC, CC, nullptr, XLN, (long)TT*CC, TDD);

    // 9. LN2
    ln_kernel<<<MTOT, 256>>>(X1, ln2_g, ln2_b, XLN2);

    // 10-12. big GLU: h = XLN2@gs_W+gs_b (N=3072); gate*SS; X2 = X1 + A@ms_W+ms_b
    gemm_kernel<0,false><<<dim3(CDD/128, MTOT/128, 1), 256>>>(
        XLN2, 0, CC, gs_W, 0, CDD, TMP, 0, CDD, gs_b, nullptr, 0, CC);
    gate_kernel<<<(long)MTOT*HHS/256, 256>>>(TMP, SS, Ab, HHS);
    gemm_kernel<2,false><<<dim3(CC/128, MTOT/128, 1), 256>>>(
        Ab, 0, HHS, ms_W, 0, CC, X2, 0, CC, ms_b, X1, 0, HHS);

    // 13-15. final GLU (no style): h = X2@r1_W+r1_b; gate; out = A@r2_W+r2_b
    gemm_kernel<0,false><<<dim3(CC/128, MTOT/128, 1), 256>>>(
        X2, 0, CC, r1_W, 0, CC, TMP, 0, CC, r1_b, nullptr, 0, CC);
    gate_kernel<<<(long)MTOT*HH1/256, 256>>>(TMP, nullptr, Ab, HH1);
    gemm_kernel<0,false><<<dim3(CC/128, MTOT/128, 1), 256>>>(
        Ab, 0, HH1, r2_W, 0, CC, out, 0, CC, r2_b, nullptr, 0, HH1);
}

// round 5
// speedup vs baseline: 1.0038x; 1.0038x over previous
#include <cuda_runtime.h>
#include <math.h>

// ---------------- problem constants ----------------
#define BB 8
#define TT 2048
#define CC 768
#define WDD 512
#define TDD 384
#define CDD 3072
#define HH1 384      // H1/2
#define HHS 1536     // CD/2
#define MTOT (BB*TT) // 16384

// ---------------- scratch (device globals; no runtime alloc) ----------------
__device__ float g_XLN [MTOT*CC];        // LN1(x)
__device__ float g_TMP [MTOT*CDD];       // pre-gate GEMM outputs (max width 3072)
__device__ float g_A   [MTOT*HHS];       // gated activations (max width 1536)
__device__ float g_H1  [MTOT*TDD];
__device__ float g_H2  [MTOT*TDD];
__device__ float g_MIX [BB*TDD*CC];
__device__ float g_X1  [MTOT*CC];
__device__ float g_XLN2[MTOT*CC];
__device__ float g_X2  [MTOT*CC];
__device__ float g_S1  [BB*HH1];
__device__ float g_S2  [BB*HH1];
__device__ float g_SS  [BB*HHS];

// ---------------- LayerNorm (one block per row, C=768) ----------------
__global__ __launch_bounds__(256) void ln_kernel(
    const float* __restrict__ X, const float* __restrict__ g,
    const float* __restrict__ b, float* __restrict__ Y)
{
    long row = blockIdx.x;
    const float* xr = X + row * CC;
    int t = threadIdx.x;
    float v0 = xr[t], v1 = xr[t + 256], v2 = xr[t + 512];
    float s  = v0 + v1 + v2;
    float s2 = v0*v0 + v1*v1 + v2*v2;
    __shared__ float sh[64];
    #pragma unroll
    for (int o = 16; o > 0; o >>= 1) {
        s  += __shfl_down_sync(0xffffffffu, s,  o);
        s2 += __shfl_down_sync(0xffffffffu, s2, o);
    }
    int w = t >> 5, l = t & 31;
    if (l == 0) { sh[w] = s; sh[w + 32] = s2; }
    __syncthreads();
    if (w == 0) {
        s  = (l < 8) ? sh[l]      : 0.f;
        s2 = (l < 8) ? sh[l + 32] : 0.f;
        #pragma unroll
        for (int o = 4; o > 0; o >>= 1) {
            s  += __shfl_down_sync(0xffffffffu, s,  o);
            s2 += __shfl_down_sync(0xffffffffu, s2, o);
        }
        if (l == 0) { sh[0] = s; sh[1] = s2; }
    }
    __syncthreads();
    float mu  = sh[0] * (1.0f / CC);
    float var = sh[1] * (1.0f / CC) - mu * mu;
    float inv = rsqrtf(var + 1e-6f);
    float* yr = Y + row * CC;
    yr[t]       = (v0 - mu) * inv * g[t]       + b[t];
    yr[t + 256] = (v1 - mu) * inv * g[t + 256] + b[t + 256];
    yr[t + 512] = (v2 - mu) * inv * g[t + 512] + b[t + 512];
}

// ---------------- style vector: S[b,n] = w_row[b] @ sW + sb ----------------
__global__ __launch_bounds__(128) void style_kernel(
    const float* __restrict__ w, int wOff,
    const float* __restrict__ sW, const float* __restrict__ sb,
    float* __restrict__ S, int N)
{
    int b = blockIdx.y;
    int n = blockIdx.x * 128 + threadIdx.x;
    const float* wr = w + (long)b * 2 * WDD + wOff;
    __shared__ float ws[WDD];
    for (int i = threadIdx.x; i < WDD; i += 128) ws[i] = wr[i];
    __syncthreads();
    float acc = sb[n];
    #pragma unroll 4
    for (int k = 0; k < WDD; k++) acc = fmaf(ws[k], sW[(long)k * N + n], acc);
    S[(long)b * N + n] = acc;
}

// ---------------- gate: A = h_a * sigmoid(h_g) [* S(b)] ----------------
__global__ __launch_bounds__(256) void gate_kernel(
    const float* __restrict__ H, const float* __restrict__ S,
    float* __restrict__ A, int Hh)
{
    long idx = (long)blockIdx.x * 256 + threadIdx.x;
    long row = idx / Hh;
    int  j   = (int)(idx - row * Hh);
    const float* hr = H + row * (2L * Hh);
    float av = hr[j];
    float gv = hr[j + Hh];
    float r  = av * (1.0f / (1.0f + expf(-gv)));
    if (S) r *= S[(row / TT) * (long)Hh + j];
    A[idx] = r;
}

// ---------------- tiled SGEMM 128x128x16, 256 thr, 8x8 micro-tile ----------------
// EPI: 0=bias(opt), 1=gelu(exact), 2=bias(opt)+residual
template<int EPI, bool TRANSA>
__global__ __launch_bounds__(256) void gemm_kernel(
    const float* __restrict__ A, long sA, int lda,
    const float* __restrict__ Bm, long sB, int ldb,
    float* __restrict__ Cm, long sC, int ldc,
    const float* __restrict__ bias,
    const float* __restrict__ Res, long sRes,
    int K)
{
    const int bz = blockIdx.z;
    A  += (long)bz * sA;
    Bm += (long)bz * sB;
    Cm += (long)bz * sC;
    if (EPI == 2) Res += (long)bz * sRes;

    const int bm = blockIdx.y * 128;
    const int bn = blockIdx.x * 128;
    const int tid = threadIdx.x;
    const int tx = tid & 15, ty = tid >> 4;

    __shared__ float As[16][128];
    __shared__ float Bs[16][128];

    float acc[8][8];
    #pragma unroll
    for (int i = 0; i < 8; i++)
        #pragma unroll
        for (int j = 0; j < 8; j++) acc[i][j] = 0.f;

    for (int k0 = 0; k0 < K; k0 += 16) {
        if (!TRANSA) {
            #pragma unroll
            for (int i = 0; i < 2; i++) {
                int t = tid + i * 256;          // 0..511
                int row = t >> 2;               // 0..127
                int kc  = (t & 3) * 4;          // 0,4,8,12
                float4 v = *(const float4*)&A[(long)(bm + row) * lda + k0 + kc];
                As[kc + 0][row] = v.x; As[kc + 1][row] = v.y;
                As[kc + 2][row] = v.z; As[kc + 3][row] = v.w;
            }
        } else {
            #pragma unroll
            for (int i = 0; i < 2; i++) {
                int t = tid + i * 256;
                int kr = t >> 5;                // 0..15
                int mc = (t & 31) * 4;          // 0..124
                *(float4*)&As[kr][mc] =
                    *(const float4*)&A[(long)(k0 + kr) * lda + bm + mc];
            }
        }
        #pragma unroll
        for (int i = 0; i < 2; i++) {
            int t = tid + i * 256;
            int kr = t >> 5;
            int nc = (t & 31) * 4;
            *(float4*)&Bs[kr][nc] =
                *(const float4*)&Bm[(long)(k0 + kr) * ldb + bn + nc];
        }
        __syncthreads();

        #pragma unroll
        for (int kk = 0; kk < 16; kk++) {
            float a[8], b[8];
            *(float4*)&a[0] = *(float4*)&As[kk][ty * 8];
            *(float4*)&a[4] = *(float4*)&As[kk][ty * 8 + 4];
            *(float4*)&b[0] = *(float4*)&Bs[kk][tx * 8];
            *(float4*)&b[4] = *(float4*)&Bs[kk][tx * 8 + 4];
            #pragma unroll
            for (int i = 0; i < 8; i++)
                #pragma unroll
                for (int j = 0; j < 8; j++)
                    acc[i][j] = fmaf(a[i], b[j], acc[i][j]);
        }
        __syncthreads();
    }

    #pragma unroll
    for (int i = 0; i < 8; i++) {
        long row = bm + ty * 8 + i;
        #pragma unroll
        for (int j = 0; j < 8; j += 4) {
            int col = bn + tx * 8 + j;
            float4 v = make_float4(acc[i][j], acc[i][j+1], acc[i][j+2], acc[i][j+3]);
            if (EPI != 1 && bias) {
                v.x += bias[col];   v.y += bias[col+1];
                v.z += bias[col+2]; v.w += bias[col+3];
            }
            if (EPI == 1) {
                v.x = 0.5f * v.x * (1.f + erff(v.x * 0.70710678118f));
                v.y = 0.5f * v.y * (1.f + erff(v.y * 0.70710678118f));
                v.z = 0.5f * v.z * (1.f + erff(v.z * 0.70710678118f));
                v.w = 0.5f * v.w * (1.f + erff(v.w * 0.70710678118f));
            }
            if (EPI == 2) {
                float4 r = *(const float4*)&Res[row * ldc + col];
                v.x += r.x; v.y += r.y; v.z += r.z; v.w += r.w;
            }
            *(float4*)&Cm[row * (long)ldc + col] = v;
        }
    }
}

// ---------------- host orchestration ----------------
extern "C" void kernel_launch(void* const* d_in, const int* in_sizes, int n_in,
                              void* d_out, int out_size)
{
    const float* x     = (const float*)d_in[0];
    const float* w     = (const float*)d_in[1];
    const float* ln1_g = (const float*)d_in[2];
    const float* ln1_b = (const float*)d_in[3];
    const float* ln2_g = (const float*)d_in[4];
    const float* ln2_b = (const float*)d_in[5];
    const float* g1_W  = (const float*)d_in[6];
    const float* g1_b  = (const float*)d_in[7];
    const float* s1_W  = (const float*)d_in[8];
    const float* s1_b  = (const float*)d_in[9];
    const float* m1_W  = (const float*)d_in[10];
    const float* m1_b  = (const float*)d_in[11];
    const float* g2_W  = (const float*)d_in[12];
    const float* g2_b  = (const float*)d_in[13];
    const float* s2_W  = (const float*)d_in[14];
    const float* s2_b  = (const float*)d_in[15];
    const float* m2_W  = (const float*)d_in[16];
    const float* m2_b  = (const float*)d_in[17];
    const float* gs_W  = (const float*)d_in[18];
    const float* gs_b  = (const float*)d_in[19];
    const float* ss_W  = (const float*)d_in[20];
    const float* ss_b  = (const float*)d_in[21];
    const float* ms_W  = (const float*)d_in[22];
    const float* ms_b  = (const float*)d_in[23];
    const float* r1_W  = (const float*)d_in[24];
    const float* r1_b  = (const float*)d_in[25];
    const float* r2_W  = (const float*)d_in[26];
    const float* r2_b  = (const float*)d_in[27];
    float* out = (float*)d_out;

    float *XLN, *TMP, *Ab, *H1, *H2, *MIX, *X1, *XLN2, *X2, *S1, *S2, *SS;
    cudaGetSymbolAddress((void**)&XLN,  g_XLN);
    cudaGetSymbolAddress((void**)&TMP,  g_TMP);
    cudaGetSymbolAddress((void**)&Ab,   g_A);
    cudaGetSymbolAddress((void**)&H1,   g_H1);
    cudaGetSymbolAddress((void**)&H2,   g_H2);
    cudaGetSymbolAddress((void**)&MIX,  g_MIX);
    cudaGetSymbolAddress((void**)&X1,   g_X1);
    cudaGetSymbolAddress((void**)&XLN2, g_XLN2);
    cudaGetSymbolAddress((void**)&X2,   g_X2);
    cudaGetSymbolAddress((void**)&S1,   g_S1);
    cudaGetSymbolAddress((void**)&S2,   g_S2);
    cudaGetSymbolAddress((void**)&SS,   g_SS);

    // 1. LN1
    ln_kernel<<<MTOT, 256>>>(x, ln1_g, ln1_b, XLN);

    // 2. style vectors (w0 for s1/s2, w1 for ss)
    style_kernel<<<dim3(HH1/128, BB), 128>>>(w, 0,   s1_W, s1_b, S1, HH1);
    style_kernel<<<dim3(HH1/128, BB), 128>>>(w, 0,   s2_W, s2_b, S2, HH1);
    style_kernel<<<dim3(HHS/128, BB), 128>>>(w, WDD, ss_W, ss_b, SS, HHS);

    // 3-5. GLU #1: h = XLN@g1_W+g1_b ; gate*S1 ; H1 = A@m1_W+m1_b
    gemm_kernel<0,false><<<dim3(CC/128, MTOT/128, 1), 256>>>(
        XLN, 0, CC, g1_W, 0, CC, TMP, 0, CC, g1_b, nullptr, 0, CC);
    gate_kernel<<<(long)MTOT*HH1/256, 256>>>(TMP, S1, Ab, HH1);
    gemm_kernel<0,false><<<dim3(TDD/128, MTOT/128, 1), 256>>>(
        Ab, 0, HH1, m1_W, 0, TDD, H1, 0, TDD, m1_b, nullptr, 0, TDD);

    // 6. GLU #2 -> H2
    gemm_kernel<0,false><<<dim3(CC/128, MTOT/128, 1), 256>>>(
        XLN, 0, CC, g2_W, 0, CC, TMP, 0, CC, g2_b, nullptr, 0, CC);
    gate_kernel<<<(long)MTOT*HH1/256, 256>>>(TMP, S2, Ab, HH1);
    gemm_kernel<0,false><<<dim3(TDD/128, MTOT/128, 1), 256>>>(
        Ab, 0, HH1, m2_W, 0, TDD, H2, 0, TDD, m2_b, nullptr, 0, TDD);

    // 7. mix[b] = gelu(h1[b]^T @ XLN[b])   (transA, batched, K=T)
    gemm_kernel<1,true><<<dim3(CC/128, TDD/128, BB), 256>>>(
        H1, (long)TT*TDD, TDD, XLN, (long)TT*CC, CC,
        MIX, (long)TDD*CC, CC, nullptr, nullptr, 0, TT);

    // 8. X1 = XLN + h2[b] @ mix[b]   (batched, K=TD)
    gemm_kernel<2,false><<<dim3(CC/128, TT/128, BB), 256>>>(
        H2, (long)TT*TDD, TDD, MIX, (long)TDD*CC, CC,
        X1, (long)TT*CC, CC, nullptr, XLN, (long)TT*CC, TDD);

    // 9. LN2
    ln_kernel<<<MTOT, 256>>>(X1, ln2_g, ln2_b, XLN2);

    // 10-12. big GLU: h = XLN2@gs_W+gs_b (N=3072); gate*SS; X2 = X1 + A@ms_W+ms_b
    gemm_kernel<0,false><<<dim3(CDD/128, MTOT/128, 1), 256>>>(
        XLN2, 0, CC, gs_W, 0, CDD, TMP, 0, CDD, gs_b, nullptr, 0, CC);
    gate_kernel<<<(long)MTOT*HHS/256, 256>>>(TMP, SS, Ab, HHS);
    gemm_kernel<2,false><<<dim3(CC/128, MTOT/128, 1), 256>>>(
        Ab, 0, HHS, ms_W, 0, CC, X2, 0, CC, ms_b, X1, 0, HHS);

    // 13-15. final GLU (no style): h = X2@r1_W+r1_b; gate; out = A@r2_W+r2_b
    gemm_kernel<0,false><<<dim3(CC/128, MTOT/128, 1), 256>>>(
        X2, 0, CC, r1_W, 0, CC, TMP, 0, CC, r1_b, nullptr, 0, CC);
    gate_kernel<<<(long)MTOT*HH1/256, 256>>>(TMP, nullptr, Ab, HH1);
    gemm_kernel<0,false><<<dim3(CC/128, MTOT/128, 1), 256>>>(
        Ab, 0, HH1, r2_W, 0, CC, out, 0, CC, r2_b, nullptr, 0, HH1);
}

// round 10
// speedup vs baseline: 2.2469x; 2.2383x over previous
#include <cuda_runtime.h>
#include <cuda_fp16.h>
#include <math.h>
#include <stdint.h>

#define BB 8
#define TT 2048
#define CC 768
#define WDD 512
#define TDD 384
#define CDD 3072
#define HH1 384
#define HHS 1536
#define MTOT (BB*TT)

typedef unsigned int uint;
typedef unsigned long long ull;

// ---------------- scratch (device globals; no runtime alloc) ----------------
__device__ __align__(16) float g_XLN [MTOT*CC];
__device__ __align__(16) float g_TMP [(size_t)MTOT*CDD];
__device__ __align__(16) float g_H1  [MTOT*TDD];
__device__ __align__(16) float g_H2  [MTOT*TDD];
__device__ __align__(16) float g_MIX [BB*TDD*CC];
__device__ __align__(16) float g_X1  [MTOT*CC];
__device__ __align__(16) float g_X2  [MTOT*CC];
__device__ __align__(16) float g_S1  [BB*HH1];
__device__ __align__(16) float g_S2  [BB*HH1];
__device__ __align__(16) float g_SS  [BB*HHS];
// fp16 split operands (A: [hi|hi|lo] along 3K, B: [hi|lo|hi] along 3K)
__device__ __align__(16) __half h_XLN [(size_t)MTOT*2304];   // [M, 3*768]
__device__ __align__(16) __half h_ACT [(size_t)MTOT*4608];   // gated, up to 3*1536
__device__ __align__(16) __half h_H2  [(size_t)MTOT*1152];   // [M, 3*384]
__device__ __align__(16) __half h_X2  [(size_t)MTOT*2304];
__device__ __align__(16) __half h_H1T [(size_t)BB*TDD*6144]; // [TD, 3*T] per batch
__device__ __align__(16) __half h_XLNT[(size_t)BB*CC*6144];  // [C, 3*T]  per batch
__device__ __align__(16) __half h_MIXT[(size_t)BB*CC*1152];  // [C, 3*TD] per batch
// fp16 split weights, [N, 3K] layout, B-order
__device__ __align__(16) __half h_Wg1[768*2304], h_Wg2[768*2304], h_Wr1[768*2304];
__device__ __align__(16) __half h_Wm1[384*1152], h_Wm2[384*1152], h_Wr2[768*1152];
__device__ __align__(16) __half h_Wgs[(size_t)3072*2304];
__device__ __align__(16) __half h_Wms[768*4608];

// ---------------- PTX helpers (generic sm_80-class only) ----------------
__device__ __forceinline__ uint s2u(const void* p){
    uint a;
    asm("{ .reg .u64 t; cvta.to.shared.u64 t, %1; cvt.u32.u64 %0, t; }":"=r"(a):"l"(p));
    return a;
}
__device__ __forceinline__ void cpa16(uint s, const void* g){
    asm volatile("cp.async.cg.shared.global [%0], [%1], 16;"::"r"(s),"l"(g));
}
__device__ __forceinline__ void cpa_commit(){ asm volatile("cp.async.commit_group;":::"memory"); }
template<int N> __device__ __forceinline__ void cpa_wait(){
    asm volatile("cp.async.wait_group %0;"::"n"(N):"memory");
}
__device__ __forceinline__ void ldsm4(uint* d, uint addr){
    asm volatile("ldmatrix.sync.aligned.m8n8.x4.shared.b16 {%0,%1,%2,%3}, [%4];"
        : "=r"(d[0]),"=r"(d[1]),"=r"(d[2]),"=r"(d[3]) : "r"(addr));
}
__device__ __forceinline__ void mma16816(float* c, const uint* a, uint b0, uint b1){
    asm volatile("mma.sync.aligned.m16n8k16.row.col.f32.f16.f16.f32 "
        "{%0,%1,%2,%3}, {%4,%5,%6,%7}, {%8,%9}, {%0,%1,%2,%3};"
        : "+f"(c[0]),"+f"(c[1]),"+f"(c[2]),"+f"(c[3])
        : "r"(a[0]),"r"(a[1]),"r"(a[2]),"r"(a[3]), "r"(b0),"r"(b1));
}

// ---------------- HMMA GEMM: C[M,N] = A[M,K'] . B[N,K']^T (fp16 in, f32 out) --
// 128x128 CTA tile, 256 thr, warp grid 2(M)x4(N), warp tile 64x32, k-stage 32,
// 3-stage cp.async pipeline, 80B smem pitch (conflict-free ldmatrix).
// EPI: 0 = +bias(opt), 1 = exact gelu, 2 = +bias(opt) + residual
#define SPITCH 40
#define STAGE_HALFS (128*SPITCH)
#define HSMEM_BYTES (3*2*STAGE_HALFS*2)   // 61440

template<int EPI>
__global__ __launch_bounds__(256) void hgemm(
    const __half* __restrict__ A, long sA, int lda,
    const __half* __restrict__ B, long sB, int ldb,
    float* __restrict__ Cm, long sC, int ldc,
    const float* __restrict__ bias,
    const float* __restrict__ Res, long sRes, int K)
{
    extern __shared__ __half sm[];
    const int tid = threadIdx.x;
    const int lane = tid & 31, wid = tid >> 5;
    const int wm = wid >> 2, wn = wid & 3;
    const int bz = blockIdx.z;
    const long bm = (long)blockIdx.y * 128;
    const long bn = (long)blockIdx.x * 128;
    const __half* Ag = A + bz * sA + bm * lda;
    const __half* Bg = B + bz * sB + bn * ldb;
    Cm += bz * sC;
    if (EPI == 2) Res += bz * sRes;

    float acc[4][4][4];
    #pragma unroll
    for (int i = 0; i < 4; i++)
        #pragma unroll
        for (int j = 0; j < 4; j++)
            #pragma unroll
            for (int q = 0; q < 4; q++) acc[i][j][q] = 0.f;

    const int ldrow = tid >> 2, ldseg = tid & 3;

    auto load_stage = [&](int s, int k0){
        __half* As = sm + s * (2 * STAGE_HALFS);
        __half* Bs = As + STAGE_HALFS;
        #pragma unroll
        for (int i = 0; i < 2; i++){
            int row = ldrow + i * 64;
            cpa16(s2u(As + row * SPITCH + ldseg * 8), Ag + (long)row * lda + k0 + ldseg * 8);
            cpa16(s2u(Bs + row * SPITCH + ldseg * 8), Bg + (long)row * ldb + k0 + ldseg * 8);
        }
    };

    const int nst = K >> 5;
    load_stage(0, 0);  cpa_commit();
    load_stage(1, 32); cpa_commit();

    for (int s = 0; s < nst; s++){
        if (s + 2 < nst) load_stage((s + 2) % 3, (s + 2) << 5);
        cpa_commit();
        cpa_wait<2>();
        __syncthreads();
        const __half* As = sm + (s % 3) * (2 * STAGE_HALFS);
        const __half* Bs = As + STAGE_HALFS;
        #pragma unroll
        for (int kk = 0; kk < 2; kk++){
            uint a[4][4], b[2][4];
            #pragma unroll
            for (int mt = 0; mt < 4; mt++){
                int r = wm * 64 + mt * 16 + (lane & 7) + ((lane >> 3) & 1) * 8;
                int sg = kk * 2 + (lane >> 4);
                ldsm4(a[mt], s2u(As + r * SPITCH + sg * 8));
            }
            #pragma unroll
            for (int bq = 0; bq < 2; bq++){
                int r = wn * 32 + bq * 16 + (lane & 7) + ((lane >> 4) & 1) * 8;
                int sg = kk * 2 + ((lane >> 3) & 1);
                ldsm4(b[bq], s2u(Bs + r * SPITCH + sg * 8));
            }
            #pragma unroll
            for (int mt = 0; mt < 4; mt++)
                #pragma unroll
                for (int nt = 0; nt < 4; nt++)
                    mma16816(acc[mt][nt], a[mt], b[nt >> 1][(nt & 1) * 2],
                             b[nt >> 1][(nt & 1) * 2 + 1]);
        }
        __syncthreads();
    }

    #pragma unroll
    for (int mt = 0; mt < 4; mt++){
        #pragma unroll
        for (int hf = 0; hf < 2; hf++){
            long row = bm + wm * 64 + mt * 16 + (lane >> 2) + hf * 8;
            float* Cr = Cm + row * (long)ldc;
            const float* Rr = (EPI == 2) ? (Res + row * (long)ldc) : nullptr;
            #pragma unroll
            for (int nt = 0; nt < 4; nt++){
                long col = bn + wn * 32 + nt * 8 + (lane & 3) * 2;
                float v0 = acc[mt][nt][hf * 2 + 0];
                float v1 = acc[mt][nt][hf * 2 + 1];
                if (EPI != 1 && bias){ v0 += bias[col]; v1 += bias[col + 1]; }
                if (EPI == 1){
                    v0 = 0.5f * v0 * (1.f + erff(v0 * 0.70710678118f));
                    v1 = 0.5f * v1 * (1.f + erff(v1 * 0.70710678118f));
                }
                if (EPI == 2){
                    float2 q = *(const float2*)&Rr[col];
                    v0 += q.x; v1 += q.y;
                }
                float2 o; o.x = v0; o.y = v1;
                *(float2*)&Cr[col] = o;
            }
        }
    }
}

// ---------------- fp16 split helpers ----------------
__device__ __forceinline__ void split1(float x, uint16_t& h, uint16_t& l){
    __half hb = __float2half_rn(x);
    h = __half_as_ushort(hb);
    l = __half_as_ushort(__float2half_rn(x - __half2float(hb)));
}
__device__ __forceinline__ void split4(float4 v, ull& hu, ull& lu){
    uint16_t h0,h1,h2,h3,l0,l1,l2,l3;
    split1(v.x,h0,l0); split1(v.y,h1,l1); split1(v.z,h2,l2); split1(v.w,h3,l3);
    hu = (ull)h0 | ((ull)h1<<16) | ((ull)h2<<32) | ((ull)h3<<48);
    lu = (ull)l0 | ((ull)l1<<16) | ((ull)l2<<32) | ((ull)l3<<48);
}

// split_row: X[R,K] f32 -> O[R,3K] fp16 [hi|hi|lo]   (block = K/4)
__global__ void split_row_kernel(const float* __restrict__ X, __half* __restrict__ O, int K){
    long r = blockIdx.x;
    int j = threadIdx.x * 4;
    float4 v = *(const float4*)&X[r * K + j];
    ull hu, lu; split4(v, hu, lu);
    __half* o = O + r * (3L * K);
    *(ull*)(o + j)          = hu;
    *(ull*)(o + K + j)      = hu;
    *(ull*)(o + 2L * K + j) = lu;
}

// gate+split: H[R,2K] -> O[R,3K] fp16 [hi|hi|lo], val = a*sigmoid(g)[*S(b)]
__global__ void gate_split_kernel(const float* __restrict__ H, const float* __restrict__ S,
                                  __half* __restrict__ O, int K){
    long r = blockIdx.x;
    int j = threadIdx.x * 4;
    const float* hr = H + r * (2L * K);
    float4 a = *(const float4*)&hr[j];
    float4 g = *(const float4*)&hr[K + j];
    float4 v;
    v.x = a.x / (1.f + expf(-g.x));
    v.y = a.y / (1.f + expf(-g.y));
    v.z = a.z / (1.f + expf(-g.z));
    v.w = a.w / (1.f + expf(-g.w));
    if (S){
        float4 s = *(const float4*)&S[(r / TT) * (long)K + j];
        v.x *= s.x; v.y *= s.y; v.z *= s.z; v.w *= s.w;
    }
    ull hu, lu; split4(v, hu, lu);
    __half* o = O + r * (3L * K);
    *(ull*)(o + j)          = hu;
    *(ull*)(o + K + j)      = hu;
    *(ull*)(o + 2L * K + j) = lu;
}

// LayerNorm: f32 row -> optional f32 + fp16 split [hi|hi|lo], C=768
__global__ __launch_bounds__(256) void ln_kernel(
    const float* __restrict__ X, const float* __restrict__ g,
    const float* __restrict__ b, float* __restrict__ Y, __half* __restrict__ O)
{
    long row = blockIdx.x;
    const float* xr = X + row * CC;
    int t = threadIdx.x;
    float v0 = xr[t], v1 = xr[t + 256], v2 = xr[t + 512];
    float s  = v0 + v1 + v2;
    float s2 = v0*v0 + v1*v1 + v2*v2;
    __shared__ float sh[64];
    #pragma unroll
    for (int o = 16; o > 0; o >>= 1){
        s  += __shfl_down_sync(0xffffffffu, s,  o);
        s2 += __shfl_down_sync(0xffffffffu, s2, o);
    }
    int w = t >> 5, l = t & 31;
    if (l == 0){ sh[w] = s; sh[w + 32] = s2; }
    __syncthreads();
    if (w == 0){
        s  = (l < 8) ? sh[l]      : 0.f;
        s2 = (l < 8) ? sh[l + 32] : 0.f;
        #pragma unroll
        for (int o = 4; o > 0; o >>= 1){
            s  += __shfl_down_sync(0xffffffffu, s,  o);
            s2 += __shfl_down_sync(0xffffffffu, s2, o);
        }
        if (l == 0){ sh[0] = s; sh[1] = s2; }
    }
    __syncthreads();
    float mu  = sh[0] * (1.0f / CC);
    float var = sh[1] * (1.0f / CC) - mu * mu;
    float inv = rsqrtf(var + 1e-6f);
    __half* orow = O + row * 2304L;
    float* yr = Y ? (Y + row * CC) : nullptr;
    #pragma unroll
    for (int q = 0; q < 3; q++){
        int j = t + q * 256;
        float y = (q == 0 ? v0 : (q == 1 ? v1 : v2));
        y = (y - mu) * inv * g[j] + b[j];
        if (Y) yr[j] = y;
        uint16_t h, lo2; split1(y, h, lo2);
        orow[j]        = __ushort_as_half(h);
        orow[768 + j]  = __ushort_as_half(h);
        orow[1536 + j] = __ushort_as_half(lo2);
    }
}

// transpose+split: X[R,Cn] f32 (batched) -> O[Cn,3R] fp16
// AORDER: [hi|hi|lo], else B-order [hi|lo|hi].  block (32,8)
template<bool AORDER>
__global__ void splitT_kernel(const float* __restrict__ X, long sIn,
                              __half* __restrict__ O, long sOut, int R, int Cn)
{
    int bz = blockIdx.z;
    X += (long)bz * sIn;  O += (long)bz * sOut;
    __shared__ float tile[32][33];
    int r0 = blockIdx.y * 32, c0 = blockIdx.x * 32;
    int tx = threadIdx.x, ty = threadIdx.y;
    #pragma unroll
    for (int i = 0; i < 32; i += 8)
        tile[ty + i][tx] = X[(long)(r0 + ty + i) * Cn + c0 + tx];
    __syncthreads();
    #pragma unroll
    for (int i = 0; i < 32; i += 8){
        int c = c0 + ty + i, r = r0 + tx;
        float v = tile[tx][ty + i];
        uint16_t h, lo2; split1(v, h, lo2);
        long base = (long)c * (3L * R);
        O[base + r] = __ushort_as_half(h);
        if (AORDER){
            O[base + R + r]      = __ushort_as_half(h);
            O[base + 2L * R + r] = __ushort_as_half(lo2);
        } else {
            O[base + R + r]      = __ushort_as_half(lo2);
            O[base + 2L * R + r] = __ushort_as_half(h);
        }
    }
}

// ---------------- style vector: S[b,n] = w_row[b] @ sW + sb ----------------
__global__ __launch_bounds__(256) void style_kernel(
    const float* __restrict__ w, int wOff,
    const float* __restrict__ sW, const float* __restrict__ sb,
    float* __restrict__ S, int N)
{
    int b = blockIdx.y;
    int nl = threadIdx.x & 63, kg = threadIdx.x >> 6;
    int n = blockIdx.x * 64 + nl;
    __shared__ float ws[WDD];
    __shared__ float red[256];
    const float* wr = w + (long)b * 2 * WDD + wOff;
    for (int i = threadIdx.x; i < WDD; i += 256) ws[i] = wr[i];
    __syncthreads();
    float acc = 0.f;
    #pragma unroll 4
    for (int k = kg * 128; k < kg * 128 + 128; k++)
        acc = fmaf(ws[k], sW[(long)k * N + n], acc);
    red[threadIdx.x] = acc;
    __syncthreads();
    if (kg == 0)
        S[(long)b * N + n] = red[nl] + red[64+nl] + red[128+nl] + red[192+nl] + sb[n];
}

// ---------------- host orchestration ----------------
extern "C" void kernel_launch(void* const* d_in, const int* in_sizes, int n_in,
                              void* d_out, int out_size)
{
    const float* x     = (const float*)d_in[0];
    const float* w     = (const float*)d_in[1];
    const float* ln1_g = (const float*)d_in[2];
    const float* ln1_b = (const float*)d_in[3];
    const float* ln2_g = (const float*)d_in[4];
    const float* ln2_b = (const float*)d_in[5];
    const float* g1_W  = (const float*)d_in[6];
    const float* g1_b  = (const float*)d_in[7];
    const float* s1_W  = (const float*)d_in[8];
    const float* s1_b  = (const float*)d_in[9];
    const float* m1_W  = (const float*)d_in[10];
    const float* m1_b  = (const float*)d_in[11];
    const float* g2_W  = (const float*)d_in[12];
    const float* g2_b  = (const float*)d_in[13];
    const float* s2_W  = (const float*)d_in[14];
    const float* s2_b  = (const float*)d_in[15];
    const float* m2_W  = (const float*)d_in[16];
    const float* m2_b  = (const float*)d_in[17];
    const float* gs_W  = (const float*)d_in[18];
    const float* gs_b  = (const float*)d_in[19];
    const float* ss_W  = (const float*)d_in[20];
    const float* ss_b  = (const float*)d_in[21];
    const float* ms_W  = (const float*)d_in[22];
    const float* ms_b  = (const float*)d_in[23];
    const float* r1_W  = (const float*)d_in[24];
    const float* r1_b  = (const float*)d_in[25];
    const float* r2_W  = (const float*)d_in[26];
    const float* r2_b  = (const float*)d_in[27];
    float* out = (float*)d_out;

    float *XLN,*TMP,*H1,*H2,*MIX,*X1,*X2,*S1,*S2,*SS;
    __half *XLNh,*ACT,*H2h,*X2h,*H1T,*XLNT,*MIXT;
    __half *Wg1,*Wg2,*Wr1,*Wm1,*Wm2,*Wr2,*Wgs,*Wms;
    cudaGetSymbolAddress((void**)&XLN, g_XLN);   cudaGetSymbolAddress((void**)&TMP, g_TMP);
    cudaGetSymbolAddress((void**)&H1, g_H1);     cudaGetSymbolAddress((void**)&H2, g_H2);
    cudaGetSymbolAddress((void**)&MIX, g_MIX);   cudaGetSymbolAddress((void**)&X1, g_X1);
    cudaGetSymbolAddress((void**)&X2, g_X2);
    cudaGetSymbolAddress((void**)&S1, g_S1);     cudaGetSymbolAddress((void**)&S2, g_S2);
    cudaGetSymbolAddress((void**)&SS, g_SS);
    cudaGetSymbolAddress((void**)&XLNh, h_XLN);  cudaGetSymbolAddress((void**)&ACT, h_ACT);
    cudaGetSymbolAddress((void**)&H2h, h_H2);    cudaGetSymbolAddress((void**)&X2h, h_X2);
    cudaGetSymbolAddress((void**)&H1T, h_H1T);   cudaGetSymbolAddress((void**)&XLNT, h_XLNT);
    cudaGetSymbolAddress((void**)&MIXT, h_MIXT);
    cudaGetSymbolAddress((void**)&Wg1, h_Wg1);   cudaGetSymbolAddress((void**)&Wg2, h_Wg2);
    cudaGetSymbolAddress((void**)&Wr1, h_Wr1);   cudaGetSymbolAddress((void**)&Wm1, h_Wm1);
    cudaGetSymbolAddress((void**)&Wm2, h_Wm2);   cudaGetSymbolAddress((void**)&Wr2, h_Wr2);
    cudaGetSymbolAddress((void**)&Wgs, h_Wgs);   cudaGetSymbolAddress((void**)&Wms, h_Wms);

    cudaFuncSetAttribute(hgemm<0>, cudaFuncAttributeMaxDynamicSharedMemorySize, HSMEM_BYTES);
    cudaFuncSetAttribute(hgemm<1>, cudaFuncAttributeMaxDynamicSharedMemorySize, HSMEM_BYTES);
    cudaFuncSetAttribute(hgemm<2>, cudaFuncAttributeMaxDynamicSharedMemorySize, HSMEM_BYTES);

    dim3 tb(32, 8);

    // weights -> [N,3K] fp16 split (B-order)
    splitT_kernel<false><<<dim3(768/32, 768/32, 1), tb>>>(g1_W, 0, Wg1, 0, 768, 768);
    splitT_kernel<false><<<dim3(768/32, 768/32, 1), tb>>>(g2_W, 0, Wg2, 0, 768, 768);
    splitT_kernel<false><<<dim3(768/32, 768/32, 1), tb>>>(r1_W, 0, Wr1, 0, 768, 768);
    splitT_kernel<false><<<dim3(384/32, 384/32, 1), tb>>>(m1_W, 0, Wm1, 0, 384, 384);
    splitT_kernel<false><<<dim3(384/32, 384/32, 1), tb>>>(m2_W, 0, Wm2, 0, 384, 384);
    splitT_kernel<false><<<dim3(768/32, 384/32, 1), tb>>>(r2_W, 0, Wr2, 0, 384, 768);
    splitT_kernel<false><<<dim3(3072/32, 768/32, 1), tb>>>(gs_W, 0, Wgs, 0, 768, 3072);
    splitT_kernel<false><<<dim3(768/32, 1536/32, 1), tb>>>(ms_W, 0, Wms, 0, 1536, 768);

    // style vectors
    style_kernel<<<dim3(HH1/64, BB), 256>>>(w, 0,   s1_W, s1_b, S1, HH1);
    style_kernel<<<dim3(HH1/64, BB), 256>>>(w, 0,   s2_W, s2_b, S2, HH1);
    style_kernel<<<dim3(HHS/64, BB), 256>>>(w, WDD, ss_W, ss_b, SS, HHS);

    // LN1 -> XLN f32 + fp16 split [M,2304]
    ln_kernel<<<MTOT, 256>>>(x, ln1_g, ln1_b, XLN, XLNh);
    // XLN^T split (B operand of mix GEMM): [C, 3T] per batch
    splitT_kernel<false><<<dim3(CC/32, TT/32, BB), tb>>>(
        XLN, (long)TT*CC, XLNT, (long)CC*6144, TT, CC);

    // GLU #1: TMP = XLN@g1_W + b ; gate*S1 ; H1 = ACT@m1_W + b
    hgemm<0><<<dim3(CC/128, MTOT/128, 1), 256, HSMEM_BYTES>>>(
        XLNh, 0, 2304, Wg1, 0, 2304, TMP, 0, CC, g1_b, nullptr, 0, 2304);
    gate_split_kernel<<<MTOT, HH1/4>>>(TMP, S1, ACT, HH1);
    hgemm<0><<<dim3(TDD/128, MTOT/128, 1), 256, HSMEM_BYTES>>>(
        ACT, 0, 1152, Wm1, 0, 1152, H1, 0, TDD, m1_b, nullptr, 0, 1152);

    // GLU #2 -> H2
    hgemm<0><<<dim3(CC/128, MTOT/128, 1), 256, HSMEM_BYTES>>>(
        XLNh, 0, 2304, Wg2, 0, 2304, TMP, 0, CC, g2_b, nullptr, 0, 2304);
    gate_split_kernel<<<MTOT, HH1/4>>>(TMP, S2, ACT, HH1);
    hgemm<0><<<dim3(TDD/128, MTOT/128, 1), 256, HSMEM_BYTES>>>(
        ACT, 0, 1152, Wm2, 0, 1152, H2, 0, TDD, m2_b, nullptr, 0, 1152);

    // splits for mix + X1
    splitT_kernel<true ><<<dim3(TDD/32, TT/32, BB), tb>>>(
        H1, (long)TT*TDD, H1T, (long)TDD*6144, TT, TDD);
    split_row_kernel<<<MTOT, TDD/4>>>(H2, H2h, TDD);

    // MIX[b] = gelu(H1[b]^T @ XLN[b])  M=384, N=768, K'=6144
    hgemm<1><<<dim3(CC/128, TDD/128, BB), 256, HSMEM_BYTES>>>(
        H1T, (long)TDD*6144, 6144, XLNT, (long)CC*6144, 6144,
        MIX, (long)TDD*CC, CC, nullptr, nullptr, 0, 6144);
    splitT_kernel<false><<<dim3(CC/32, TDD/32, BB), tb>>>(
        MIX, (long)TDD*CC, MIXT, (long)CC*1152, TDD, CC);

    // X1[b] = XLN[b] + H2[b] @ MIX[b]  M=2048, N=768, K'=1152
    hgemm<2><<<dim3(CC/128, TT/128, BB), 256, HSMEM_BYTES>>>(
        H2h, (long)TT*1152, 1152, MIXT, (long)CC*1152, 1152,
        X1, (long)TT*CC, CC, nullptr, XLN, (long)TT*CC, 1152);

    // LN2 -> fp16 split only
    ln_kernel<<<MTOT, 256>>>(X1, ln2_g, ln2_b, nullptr, XLNh);

    // big GLU: TMP = XLN2@gs_W + b (N=3072); gate*SS; X2 = X1 + ACT@ms_W + b
    hgemm<0><<<dim3(CDD/128, MTOT/128, 1), 256, HSMEM_BYTES>>>(
        XLNh, 0, 2304, Wgs, 0, 2304, TMP, 0, CDD, gs_b, nullptr, 0, 2304);
    gate_split_kernel<<<MTOT, HHS/4>>>(TMP, SS, ACT, HHS);
    hgemm<2><<<dim3(CC/128, MTOT/128, 1), 256, HSMEM_BYTES>>>(
        ACT, 0, 4608, Wms, 0, 4608, X2, 0, CC, ms_b, X1, 0, 4608);

    // final GLU: TMP = X2@r1_W + b ; gate ; out = ACT@r2_W + b
    split_row_kernel<<<MTOT, CC/4>>>(X2, X2h, CC);
    hgemm<0><<<dim3(CC/128, MTOT/128, 1), 256, HSMEM_BYTES>>>(
        X2h, 0, 2304, Wr1, 0, 2304, TMP, 0, CC, r1_b, nullptr, 0, 2304);
    gate_split_kernel<<<MTOT, HH1/4>>>(TMP, nullptr, ACT, HH1);
    hgemm<0><<<dim3(CC/128, MTOT/128, 1), 256, HSMEM_BYTES>>>(
        ACT, 0, 1152, Wr2, 0, 1152, out, 0, CC, r2_b, nullptr, 0, 1152);
}